// round 4
// baseline (speedup 1.0000x reference)
#include <cuda_runtime.h>

// Multi-class hinge (Crammer-Singer) loss, summed over batch.
// outputs: [N, C] fp32, labels: [N] int32, out: scalar fp32.
//
// sum_{i,j != y_i} max(outputs[i,j] - outputs[i,y_i] + 1, 0)
// The j == y_i term contributes exactly 1.0: sum over all j, subtract 1/row.
//
// Persistent grid-stride (2048 CTAs x 8 rows) with a 1-deep software
// pipeline on the dependent label->gather chain: the next row's ground-truth
// value is fetched at the top of the current iteration, so its ~1000-cycle
// dependent latency is hidden behind ~7500 cycles of streaming.

static constexpr int C_DIM   = 4096;
static constexpr int THREADS = 256;          // 4096 / (4*256) = 4 float4 per thread
static constexpr int GRID    = 2048;         // 16384 rows / 8 rows per CTA

__global__ void zero_out_kernel(float* out) {
    if (threadIdx.x == 0) out[0] = 0.0f;
}

__global__ __launch_bounds__(THREADS) void hinge_loss_kernel(
    const float* __restrict__ outputs,
    const int* __restrict__ labels,
    float* __restrict__ out,
    int N)
{
    const int tid = threadIdx.x;
    float acc = 0.0f;

    int row = blockIdx.x;
    float g = 0.0f;
    if (row < N) {
        const int lab = __ldg(labels + row);
        g = __ldg(outputs + (size_t)row * C_DIM + (size_t)lab);
    }

    while (row < N) {
        // ---- prefetch next row's ground-truth (dependent chain, 1 iter ahead)
        const int next = row + GRID;
        float ng = 0.0f;
        if (next < N) {
            const int nlab = __ldg(labels + next);
            ng = __ldg(outputs + (size_t)next * C_DIM + (size_t)nlab);
        }

        // ---- stream current row
        const float4* rowp =
            reinterpret_cast<const float4*>(outputs + (size_t)row * C_DIM);
        const float t = 1.0f - g;               // margin = max(o + t, 0)

        float4 v0 = rowp[tid];
        float4 v1 = rowp[tid + THREADS];
        float4 v2 = rowp[tid + 2 * THREADS];
        float4 v3 = rowp[tid + 3 * THREADS];

        float s = 0.0f;
        s += fmaxf(v0.x + t, 0.0f); s += fmaxf(v0.y + t, 0.0f);
        s += fmaxf(v0.z + t, 0.0f); s += fmaxf(v0.w + t, 0.0f);
        s += fmaxf(v1.x + t, 0.0f); s += fmaxf(v1.y + t, 0.0f);
        s += fmaxf(v1.z + t, 0.0f); s += fmaxf(v1.w + t, 0.0f);
        s += fmaxf(v2.x + t, 0.0f); s += fmaxf(v2.y + t, 0.0f);
        s += fmaxf(v2.z + t, 0.0f); s += fmaxf(v2.w + t, 0.0f);
        s += fmaxf(v3.x + t, 0.0f); s += fmaxf(v3.y + t, 0.0f);
        s += fmaxf(v3.z + t, 0.0f); s += fmaxf(v3.w + t, 0.0f);

        acc += s;
        if (tid == 0) acc -= 1.0f;              // remove j == label term

        row = next;
        g = ng;
    }

    // warp reduce
    #pragma unroll
    for (int o = 16; o > 0; o >>= 1)
        acc += __shfl_xor_sync(0xFFFFFFFFu, acc, o);

    __shared__ float ws[THREADS / 32];
    if ((tid & 31) == 0) ws[tid >> 5] = acc;
    __syncthreads();

    if (tid == 0) {
        float v = ws[0];
        #pragma unroll
        for (int w = 1; w < THREADS / 32; w++) v += ws[w];
        atomicAdd(out, v);
    }
}

extern "C" void kernel_launch(void* const* d_in, const int* in_sizes, int n_in,
                              void* d_out, int out_size) {
    const float* outputs = (const float*)d_in[0];
    const int* labels = (const int*)d_in[1];
    float* out = (float*)d_out;

    const int N = in_sizes[1];          // 16384 labels

    zero_out_kernel<<<1, 32>>>(out);
    hinge_loss_kernel<<<GRID, THREADS>>>(outputs, labels, out, N);
}

// round 5
// speedup vs baseline: 1.0980x; 1.0980x over previous
#include <cuda_runtime.h>

// Multi-class hinge (Crammer-Singer) loss, summed over batch.
// outputs: [N, C] fp32, labels: [N] int32, out: scalar fp32.
//
// sum_{i,j != y_i} max(outputs[i,j] - outputs[i,y_i] + 1, 0)
// The j == y_i term contributes exactly 1.0: sum over all j, subtract 1/row.
//
// One CTA per row (one-shot, 16384 CTAs: best measured DRAM% — persistent
// variants regressed). The ground-truth value is NOT gathered via a dependent
// LDG; the owning thread publishes it from its already-loaded registers via
// shared memory, so the label load and the 4 streaming float4 loads are all
// independent -> pure streaming critical path.

static constexpr int C_DIM   = 4096;
static constexpr int THREADS = 256;          // 4096 / (4*256) = 4 float4 per thread

__global__ void zero_out_kernel(float* out) {
    if (threadIdx.x == 0) out[0] = 0.0f;
}

__global__ __launch_bounds__(THREADS) void hinge_loss_kernel(
    const float* __restrict__ outputs,
    const int* __restrict__ labels,
    float* __restrict__ out)
{
    const int row = blockIdx.x;
    const int tid = threadIdx.x;
    const float4* rowp =
        reinterpret_cast<const float4*>(outputs + (size_t)row * C_DIM);

    // All five loads below are independent — issue together.
    const int lab = __ldg(labels + row);
    float4 v0 = rowp[tid];
    float4 v1 = rowp[tid + THREADS];
    float4 v2 = rowp[tid + 2 * THREADS];
    float4 v3 = rowp[tid + 3 * THREADS];

    // Broadcast the ground-truth value from the owning thread's registers.
    __shared__ float sg;
    const int f = lab >> 2;                   // float4 index within the row
    if (tid == (f & (THREADS - 1))) {
        const int chunk = f >> 8;             // which of v0..v3
        float4 v = (chunk == 0) ? v0 : (chunk == 1) ? v1 : (chunk == 2) ? v2 : v3;
        const float* e = reinterpret_cast<const float*>(&v);
        sg = e[lab & 3];
    }
    __syncthreads();
    const float t = 1.0f - sg;                // margin = max(o + t, 0)

    float s = 0.0f;
    s += fmaxf(v0.x + t, 0.0f); s += fmaxf(v0.y + t, 0.0f);
    s += fmaxf(v0.z + t, 0.0f); s += fmaxf(v0.w + t, 0.0f);
    s += fmaxf(v1.x + t, 0.0f); s += fmaxf(v1.y + t, 0.0f);
    s += fmaxf(v1.z + t, 0.0f); s += fmaxf(v1.w + t, 0.0f);
    s += fmaxf(v2.x + t, 0.0f); s += fmaxf(v2.y + t, 0.0f);
    s += fmaxf(v2.z + t, 0.0f); s += fmaxf(v2.w + t, 0.0f);
    s += fmaxf(v3.x + t, 0.0f); s += fmaxf(v3.y + t, 0.0f);
    s += fmaxf(v3.z + t, 0.0f); s += fmaxf(v3.w + t, 0.0f);

    // warp reduce
    #pragma unroll
    for (int o = 16; o > 0; o >>= 1)
        s += __shfl_xor_sync(0xFFFFFFFFu, s, o);

    __shared__ float ws[THREADS / 32];
    if ((tid & 31) == 0) ws[tid >> 5] = s;
    __syncthreads();

    if (tid == 0) {
        float v = ws[0];
        #pragma unroll
        for (int w = 1; w < THREADS / 32; w++) v += ws[w];
        // subtract the j == label contribution (exactly 1.0)
        atomicAdd(out, v - 1.0f);
    }
}

extern "C" void kernel_launch(void* const* d_in, const int* in_sizes, int n_in,
                              void* d_out, int out_size) {
    const float* outputs = (const float*)d_in[0];
    const int* labels = (const int*)d_in[1];
    float* out = (float*)d_out;

    const int N = in_sizes[1];          // 16384 labels

    zero_out_kernel<<<1, 32>>>(out);
    hinge_loss_kernel<<<N, THREADS>>>(outputs, labels, out);
}